// round 3
// baseline (speedup 1.0000x reference)
#include <cuda_runtime.h>
#include <cstdint>

#define N_NODES 100000
#define N_EDGES 1200000
#define DIM 64
#define PAD 66
#define TILE 64

// Scratch (allocation-free rule: __device__ globals). 16B alignment for
// float4 stores in k_zero and red.global.add.v4.f32 in k_edge.
__device__ __align__(16) float g_A[N_NODES * DIM];  // sum_{e:dst=v} x[src]
__device__ __align__(16) float g_B[N_NODES * DIM];  // sum_{e:dst=v} x[src]*dinv[src]
__device__ float g_sdeg[N_NODES];                   // sum_{e:dst=v} dinv[src]
__device__ int   g_deg[N_NODES];                    // in-degree

typedef unsigned long long ull;

__device__ __forceinline__ ull fma2(ull a, ull b, ull c) {
    ull d;
    asm("fma.rn.f32x2 %0, %1, %2, %3;" : "=l"(d) : "l"(a), "l"(b), "l"(c));
    return d;
}
__device__ __forceinline__ float lo32(ull v) { return __uint_as_float((unsigned)v); }
__device__ __forceinline__ float hi32(ull v) { return __uint_as_float((unsigned)(v >> 32)); }
__device__ __forceinline__ float eluf(float z) { return z > 0.f ? z : expm1f(z); }

__global__ void k_zero() {
    int i = blockIdx.x * blockDim.x + threadIdx.x;
    if (i < N_NODES * DIM / 4) {
        ((float4*)g_A)[i] = make_float4(0.f, 0.f, 0.f, 0.f);
        ((float4*)g_B)[i] = make_float4(0.f, 0.f, 0.f, 0.f);
    }
    if (i < N_NODES) { g_deg[i] = 0; g_sdeg[i] = 0.f; }
}

// edge_index is int32 on device (JAX x64 disabled downgrades jnp.int64).
__global__ void k_deg(const int* __restrict__ ei) {
    int e = blockIdx.x * blockDim.x + threadIdx.x;
    if (e < N_EDGES) atomicAdd(&g_deg[ei[N_EDGES + e]], 1);
}

// Half-warp per edge: 16 lanes x float4 = 64 dims. Vector reds (v4.f32) to L2.
__global__ void k_edge(const float* __restrict__ x, const int* __restrict__ ei) {
    int t = blockIdx.x * blockDim.x + threadIdx.x;
    int e = t >> 4;
    if (e >= N_EDGES) return;
    int lane = t & 15;
    int s = ei[e];
    int d = ei[N_EDGES + e];
    float ds = rsqrtf((float)(g_deg[s] + 1));
    float4 xs = ((const float4*)x)[s * 16 + lane];
    float* pa = g_A + d * DIM + lane * 4;
    float* pb = g_B + d * DIM + lane * 4;
    asm volatile("red.global.add.v4.f32 [%0], {%1,%2,%3,%4};"
                 :: "l"(pa), "f"(xs.x), "f"(xs.y), "f"(xs.z), "f"(xs.w) : "memory");
    asm volatile("red.global.add.v4.f32 [%0], {%1,%2,%3,%4};"
                 :: "l"(pb), "f"(xs.x * ds), "f"(xs.y * ds), "f"(xs.z * ds), "f"(xs.w * ds) : "memory");
    if (lane == 0) atomicAdd(&g_sdeg[d], ds);
}

// Fused epilogue: per 64-node tile, 4 matvec streams via packed f32x2 FMAs.
//   gcn_pre = p@Wgcn + b_gcn*c1   where p = dinv*(B + dinv*x), c1 = dinv*sdeg + dinv^2
//   sage_pre = x@Wself + m@Wneigh + b_sage   where m = A * (1/max(deg,1))
//   gin_pre  = (x+A)@Wgin + b_gin
//   out = w0*elu(gcn) + w1*elu(sage) + w2*elu(gin)
__global__ void __launch_bounds__(256, 1) k_final(
    const float* __restrict__ x,
    const float* __restrict__ wts,
    const float* __restrict__ Wg,  const float* __restrict__ bg,
    const float* __restrict__ Wss, const float* __restrict__ Wsn, const float* __restrict__ bs,
    const float* __restrict__ Wi,  const float* __restrict__ bi,
    float* __restrict__ out)
{
    extern __shared__ float sh[];
    float* sWg = sh;                  // [64][PAD] transposed: sWg[c*PAD+k] = Wg[k][c]
    float* sWs = sWg + TILE * PAD;
    float* sWn = sWs + TILE * PAD;
    float* sWi = sWn + TILE * PAD;
    float* sP  = sWi + TILE * PAD;    // [64 nodes][PAD]
    float* sX  = sP  + TILE * PAD;
    float* sM  = sX  + TILE * PAD;
    float* sG  = sM  + TILE * PAD;
    float* sBg = sG  + TILE * PAD;    // [64]
    float* sBs = sBg + 64;
    float* sBi = sBs + 64;
    float* sC1 = sBi + 64;
    float* sDi = sC1 + 64;
    float* sRd = sDi + 64;

    int tid = threadIdx.x;
    int n0 = blockIdx.x * TILE;

    // Load 4 weight matrices transposed into padded shared
    for (int idx = tid; idx < 4096; idx += 256) {
        int k = idx >> 6, c = idx & 63;
        int o = c * PAD + k;
        sWg[o] = Wg[idx];
        sWs[o] = Wss[idx];
        sWn[o] = Wsn[idx];
        sWi[o] = Wi[idx];
    }
    if (tid < 64) {
        sBg[tid] = bg[tid]; sBs[tid] = bs[tid]; sBi[tid] = bi[tid];
        int n = n0 + tid;
        float dg = 0.f, sd = 0.f;
        if (n < N_NODES) { dg = (float)g_deg[n]; sd = g_sdeg[n]; }
        float dinv = rsqrtf(dg + 1.f);
        sC1[tid] = dinv * sd + dinv * dinv;
        sDi[tid] = dinv;
        sRd[tid] = 1.f / fmaxf(dg, 1.f);
    }
    __syncthreads();

    // Precompute node-vector tiles p, x, m, x+A
    for (int f = tid; f < 1024; f += 256) {
        int r = f >> 4, q = f & 15;
        int n = n0 + r;
        float4 x4 = make_float4(0.f, 0.f, 0.f, 0.f), a4 = x4, b4 = x4;
        if (n < N_NODES) {
            x4 = ((const float4*)x)[n * 16 + q];
            a4 = ((const float4*)g_A)[n * 16 + q];
            b4 = ((const float4*)g_B)[n * 16 + q];
        }
        float dinv = sDi[r], rdeg = sRd[r];
        int o = r * PAD + q * 4;
        sP[o + 0] = dinv * (b4.x + dinv * x4.x);
        sP[o + 1] = dinv * (b4.y + dinv * x4.y);
        sP[o + 2] = dinv * (b4.z + dinv * x4.z);
        sP[o + 3] = dinv * (b4.w + dinv * x4.w);
        sX[o + 0] = x4.x; sX[o + 1] = x4.y; sX[o + 2] = x4.z; sX[o + 3] = x4.w;
        sM[o + 0] = a4.x * rdeg; sM[o + 1] = a4.y * rdeg;
        sM[o + 2] = a4.z * rdeg; sM[o + 3] = a4.w * rdeg;
        sG[o + 0] = x4.x + a4.x; sG[o + 1] = x4.y + a4.y;
        sG[o + 2] = x4.z + a4.z; sG[o + 3] = x4.w + a4.w;
    }
    __syncthreads();

    // Register-tiled matvecs: thread = (tx: 4 cols {tx+16j}, ty: 4 nodes {4ty+i}),
    // k packed in pairs inside f32x2 lanes.
    int tx = tid & 15, ty = tid >> 4;
    ull aG[4][4], aS[4][4], aI[4][4];
    #pragma unroll
    for (int i = 0; i < 4; i++)
        #pragma unroll
        for (int j = 0; j < 4; j++) { aG[i][j] = 0ull; aS[i][j] = 0ull; aI[i][j] = 0ull; }

    #pragma unroll 1
    for (int kp = 0; kp < 32; kp++) {
        ull pv[4], xv[4], mv[4], gv[4];
        #pragma unroll
        for (int i = 0; i < 4; i++) {
            int o = (4 * ty + i) * PAD + 2 * kp;
            pv[i] = *(const ull*)(sP + o);
            xv[i] = *(const ull*)(sX + o);
            mv[i] = *(const ull*)(sM + o);
            gv[i] = *(const ull*)(sG + o);
        }
        ull wg[4], ws[4], wn[4], wi[4];
        #pragma unroll
        for (int j = 0; j < 4; j++) {
            int o = (tx + 16 * j) * PAD + 2 * kp;
            wg[j] = *(const ull*)(sWg + o);
            ws[j] = *(const ull*)(sWs + o);
            wn[j] = *(const ull*)(sWn + o);
            wi[j] = *(const ull*)(sWi + o);
        }
        #pragma unroll
        for (int i = 0; i < 4; i++)
            #pragma unroll
            for (int j = 0; j < 4; j++) {
                aG[i][j] = fma2(pv[i], wg[j], aG[i][j]);
                aS[i][j] = fma2(xv[i], ws[j], aS[i][j]);
                aS[i][j] = fma2(mv[i], wn[j], aS[i][j]);
                aI[i][j] = fma2(gv[i], wi[j], aI[i][j]);
            }
    }

    float w0 = wts[0], w1 = wts[1], w2 = wts[2];
    #pragma unroll
    for (int i = 0; i < 4; i++) {
        int r = 4 * ty + i, n = n0 + r;
        if (n >= N_NODES) continue;
        #pragma unroll
        for (int j = 0; j < 4; j++) {
            int c = tx + 16 * j;
            float gcn = lo32(aG[i][j]) + hi32(aG[i][j]) + sBg[c] * sC1[r];
            float sag = lo32(aS[i][j]) + hi32(aS[i][j]) + sBs[c];
            float gin = lo32(aI[i][j]) + hi32(aI[i][j]) + sBi[c];
            out[n * DIM + c] = w0 * eluf(gcn) + w1 * eluf(sag) + w2 * eluf(gin);
        }
    }
}

static const int SMEM_FINAL = (8 * TILE * PAD + 6 * 64) * (int)sizeof(float);

extern "C" void kernel_launch(void* const* d_in, const int* in_sizes, int n_in,
                              void* d_out, int out_size) {
    const float* x   = (const float*)d_in[0];
    // d_in[1] = x0 (unused: with_linear=False path)
    const float* wts = (const float*)d_in[2];
    const int* ei    = (const int*)d_in[3];   // int32! (JAX x64 disabled)
    const float* Wg  = (const float*)d_in[4];
    const float* bg  = (const float*)d_in[5];
    const float* Wss = (const float*)d_in[6];
    const float* Wsn = (const float*)d_in[7];
    const float* bs  = (const float*)d_in[8];
    const float* Wi  = (const float*)d_in[9];
    const float* bi  = (const float*)d_in[10];
    float* out = (float*)d_out;

    cudaFuncSetAttribute(k_final, cudaFuncAttributeMaxDynamicSharedMemorySize, SMEM_FINAL);

    k_zero<<<(N_NODES * DIM / 4 + 255) / 256, 256>>>();
    k_deg<<<(N_EDGES + 255) / 256, 256>>>(ei);
    k_edge<<<(N_EDGES * 16 + 255) / 256, 256>>>(x, ei);
    k_final<<<(N_NODES + TILE - 1) / TILE, 256, SMEM_FINAL>>>(
        x, wts, Wg, bg, Wss, Wsn, bs, Wi, bi, out);
}

// round 4
// speedup vs baseline: 1.1662x; 1.1662x over previous
#include <cuda_runtime.h>
#include <cstdint>

#define N_NODES 100000
#define N_EDGES 1200000
#define DIM 64
#define PAD 66
#define ROWS 128   // nodes per block tile

// Scratch (allocation-free rule: __device__ globals). 16B alignment for
// float4 stores in k_zero and red.global.add.v4.f32 in k_edge.
__device__ __align__(16) float g_A[N_NODES * DIM];  // sum_{e:dst=v} x[src]
__device__ __align__(16) float g_B[N_NODES * DIM];  // sum_{e:dst=v} x[src]*dinv[src]
__device__ float g_sdeg[N_NODES];                   // sum_{e:dst=v} dinv[src]
__device__ int   g_deg[N_NODES];                    // in-degree

typedef unsigned long long ull;

__device__ __forceinline__ ull fma2(ull a, ull b, ull c) {
    ull d;
    asm("fma.rn.f32x2 %0, %1, %2, %3;" : "=l"(d) : "l"(a), "l"(b), "l"(c));
    return d;
}
__device__ __forceinline__ float lo32(ull v) { return __uint_as_float((unsigned)v); }
__device__ __forceinline__ float hi32(ull v) { return __uint_as_float((unsigned)(v >> 32)); }
__device__ __forceinline__ float eluf(float z) { return z > 0.f ? z : expm1f(z); }

__global__ void k_zero() {
    int i = blockIdx.x * blockDim.x + threadIdx.x;
    if (i < N_NODES * DIM / 4) {
        ((float4*)g_A)[i] = make_float4(0.f, 0.f, 0.f, 0.f);
        ((float4*)g_B)[i] = make_float4(0.f, 0.f, 0.f, 0.f);
    }
    if (i < N_NODES) { g_deg[i] = 0; g_sdeg[i] = 0.f; }
}

// edge_index is int32 on device (JAX x64 disabled downgrades jnp.int64).
__global__ void k_deg(const int* __restrict__ ei) {
    int e = blockIdx.x * blockDim.x + threadIdx.x;
    if (e < N_EDGES) atomicAdd(&g_deg[ei[N_EDGES + e]], 1);
}

// Half-warp per edge: 16 lanes x float4 = 64 dims. Vector reds (v4.f32) to L2.
__global__ void k_edge(const float* __restrict__ x, const int* __restrict__ ei) {
    int t = blockIdx.x * blockDim.x + threadIdx.x;
    int e = t >> 4;
    if (e >= N_EDGES) return;
    int lane = t & 15;
    int s = ei[e];
    int d = ei[N_EDGES + e];
    float ds = rsqrtf((float)(g_deg[s] + 1));
    float4 xs = ((const float4*)x)[s * 16 + lane];
    float* pa = g_A + d * DIM + lane * 4;
    float* pb = g_B + d * DIM + lane * 4;
    asm volatile("red.global.add.v4.f32 [%0], {%1,%2,%3,%4};"
                 :: "l"(pa), "f"(xs.x), "f"(xs.y), "f"(xs.z), "f"(xs.w) : "memory");
    asm volatile("red.global.add.v4.f32 [%0], {%1,%2,%3,%4};"
                 :: "l"(pb), "f"(xs.x * ds), "f"(xs.y * ds), "f"(xs.z * ds), "f"(xs.w * ds) : "memory");
    if (lane == 0) atomicAdd(&g_sdeg[d], ds);
}

// Fused epilogue v2: 128-node tiles, 512 threads, 3 sequential matvec passes
// (gcn / sage / gin) so the live register set stays small and ptxas can
// software-pipeline the LDS.64 loads (pragma unroll 4) with 4 warps/SMSP.
//   gcn_pre = p@Wgcn + b_gcn*c1   where p = dinv*(B + dinv*x), c1 = dinv*sdeg + dinv^2
//   sage_pre = x@Wself + m@Wneigh + b_sage   where m = A * (1/max(deg,1))
//   gin_pre  = (x+A)@Wgin + b_gin
//   out = w0*elu(gcn) + w1*elu(sage) + w2*elu(gin)
__global__ void __launch_bounds__(512, 1) k_final(
    const float* __restrict__ x,
    const float* __restrict__ wts,
    const float* __restrict__ Wg,  const float* __restrict__ bg,
    const float* __restrict__ Wss, const float* __restrict__ Wsn, const float* __restrict__ bs,
    const float* __restrict__ Wi,  const float* __restrict__ bi,
    float* __restrict__ out)
{
    extern __shared__ float sh[];
    float* sWg = sh;                  // [64][PAD] transposed: sWg[c*PAD+k] = Wg[k][c]
    float* sWs = sWg + 64 * PAD;
    float* sWn = sWs + 64 * PAD;
    float* sWi = sWn + 64 * PAD;
    float* sP  = sWi + 64 * PAD;      // [ROWS][PAD] node tiles
    float* sX  = sP  + ROWS * PAD;
    float* sM  = sX  + ROWS * PAD;
    float* sG  = sM  + ROWS * PAD;
    float* sBg = sG  + ROWS * PAD;    // [64]
    float* sBs = sBg + 64;
    float* sBi = sBs + 64;
    float* sC1 = sBi + 64;            // [ROWS]
    float* sDi = sC1 + ROWS;
    float* sRd = sDi + ROWS;

    int tid = threadIdx.x;
    int n0 = blockIdx.x * ROWS;

    // Weights transposed into padded shared (coalesced gmem reads)
    for (int idx = tid; idx < 4096; idx += 512) {
        int k = idx >> 6, c = idx & 63;
        int o = c * PAD + k;
        sWg[o] = Wg[idx];
        sWs[o] = Wss[idx];
        sWn[o] = Wsn[idx];
        sWi[o] = Wi[idx];
    }
    if (tid < 64) { sBg[tid] = bg[tid]; sBs[tid] = bs[tid]; sBi[tid] = bi[tid]; }
    if (tid < ROWS) {
        int n = n0 + tid;
        float dg = 0.f, sd = 0.f;
        if (n < N_NODES) { dg = (float)g_deg[n]; sd = g_sdeg[n]; }
        float dinv = rsqrtf(dg + 1.f);
        sC1[tid] = dinv * sd + dinv * dinv;
        sDi[tid] = dinv;
        sRd[tid] = 1.f / fmaxf(dg, 1.f);
    }
    __syncthreads();

    // Fill node tiles p, x, m, x+A
    for (int f = tid; f < ROWS * 16; f += 512) {
        int r = f >> 4, q = f & 15;
        int n = n0 + r;
        float4 x4 = make_float4(0.f, 0.f, 0.f, 0.f), a4 = x4, b4 = x4;
        if (n < N_NODES) {
            x4 = ((const float4*)x)[n * 16 + q];
            a4 = ((const float4*)g_A)[n * 16 + q];
            b4 = ((const float4*)g_B)[n * 16 + q];
        }
        float dinv = sDi[r], rdeg = sRd[r];
        int o = r * PAD + q * 4;
        sP[o + 0] = dinv * (b4.x + dinv * x4.x);
        sP[o + 1] = dinv * (b4.y + dinv * x4.y);
        sP[o + 2] = dinv * (b4.z + dinv * x4.z);
        sP[o + 3] = dinv * (b4.w + dinv * x4.w);
        sX[o + 0] = x4.x; sX[o + 1] = x4.y; sX[o + 2] = x4.z; sX[o + 3] = x4.w;
        sM[o + 0] = a4.x * rdeg; sM[o + 1] = a4.y * rdeg;
        sM[o + 2] = a4.z * rdeg; sM[o + 3] = a4.w * rdeg;
        sG[o + 0] = x4.x + a4.x; sG[o + 1] = x4.y + a4.y;
        sG[o + 2] = x4.z + a4.z; sG[o + 3] = x4.w + a4.w;
    }
    __syncthreads();

    // thread = (tx: cols {tx+16j}, ty: rows {4ty+i}), k packed in f32x2 pairs.
    int tx = tid & 15, ty = tid >> 4;   // ty in 0..31
    int rbase = 4 * ty;

    float rG[4][4], rS[4][4], rI[4][4];

    // ---- pass 1: gcn = P @ Wg ----
    {
        ull acc[4][4];
        #pragma unroll
        for (int i = 0; i < 4; i++)
            #pragma unroll
            for (int j = 0; j < 4; j++) acc[i][j] = 0ull;
        #pragma unroll 4
        for (int kp = 0; kp < 32; kp++) {
            ull nv[4], wv[4];
            #pragma unroll
            for (int i = 0; i < 4; i++) nv[i] = *(const ull*)(sP + (rbase + i) * PAD + 2 * kp);
            #pragma unroll
            for (int j = 0; j < 4; j++) wv[j] = *(const ull*)(sWg + (tx + 16 * j) * PAD + 2 * kp);
            #pragma unroll
            for (int i = 0; i < 4; i++)
                #pragma unroll
                for (int j = 0; j < 4; j++) acc[i][j] = fma2(nv[i], wv[j], acc[i][j]);
        }
        #pragma unroll
        for (int i = 0; i < 4; i++)
            #pragma unroll
            for (int j = 0; j < 4; j++) rG[i][j] = lo32(acc[i][j]) + hi32(acc[i][j]);
    }

    // ---- pass 2: sage = X @ Ws + M @ Wn ----
    {
        ull acc[4][4];
        #pragma unroll
        for (int i = 0; i < 4; i++)
            #pragma unroll
            for (int j = 0; j < 4; j++) acc[i][j] = 0ull;
        #pragma unroll 2
        for (int kp = 0; kp < 32; kp++) {
            ull xv[4], mv[4], ws[4], wn[4];
            #pragma unroll
            for (int i = 0; i < 4; i++) {
                int o = (rbase + i) * PAD + 2 * kp;
                xv[i] = *(const ull*)(sX + o);
                mv[i] = *(const ull*)(sM + o);
            }
            #pragma unroll
            for (int j = 0; j < 4; j++) {
                int o = (tx + 16 * j) * PAD + 2 * kp;
                ws[j] = *(const ull*)(sWs + o);
                wn[j] = *(const ull*)(sWn + o);
            }
            #pragma unroll
            for (int i = 0; i < 4; i++)
                #pragma unroll
                for (int j = 0; j < 4; j++) {
                    acc[i][j] = fma2(xv[i], ws[j], acc[i][j]);
                    acc[i][j] = fma2(mv[i], wn[j], acc[i][j]);
                }
        }
        #pragma unroll
        for (int i = 0; i < 4; i++)
            #pragma unroll
            for (int j = 0; j < 4; j++) rS[i][j] = lo32(acc[i][j]) + hi32(acc[i][j]);
    }

    // ---- pass 3: gin = (X+A) @ Wi ----
    {
        ull acc[4][4];
        #pragma unroll
        for (int i = 0; i < 4; i++)
            #pragma unroll
            for (int j = 0; j < 4; j++) acc[i][j] = 0ull;
        #pragma unroll 4
        for (int kp = 0; kp < 32; kp++) {
            ull nv[4], wv[4];
            #pragma unroll
            for (int i = 0; i < 4; i++) nv[i] = *(const ull*)(sG + (rbase + i) * PAD + 2 * kp);
            #pragma unroll
            for (int j = 0; j < 4; j++) wv[j] = *(const ull*)(sWi + (tx + 16 * j) * PAD + 2 * kp);
            #pragma unroll
            for (int i = 0; i < 4; i++)
                #pragma unroll
                for (int j = 0; j < 4; j++) acc[i][j] = fma2(nv[i], wv[j], acc[i][j]);
        }
        #pragma unroll
        for (int i = 0; i < 4; i++)
            #pragma unroll
            for (int j = 0; j < 4; j++) rI[i][j] = lo32(acc[i][j]) + hi32(acc[i][j]);
    }

    float w0 = wts[0], w1 = wts[1], w2 = wts[2];
    #pragma unroll
    for (int i = 0; i < 4; i++) {
        int r = rbase + i, n = n0 + r;
        if (n >= N_NODES) continue;
        #pragma unroll
        for (int j = 0; j < 4; j++) {
            int c = tx + 16 * j;
            float gcn = rG[i][j] + sBg[c] * sC1[r];
            float sag = rS[i][j] + sBs[c];
            float gin = rI[i][j] + sBi[c];
            out[n * DIM + c] = w0 * eluf(gcn) + w1 * eluf(sag) + w2 * eluf(gin);
        }
    }
}

static const int SMEM_FINAL =
    (4 * 64 * PAD + 4 * ROWS * PAD + 3 * 64 + 3 * ROWS) * (int)sizeof(float);

extern "C" void kernel_launch(void* const* d_in, const int* in_sizes, int n_in,
                              void* d_out, int out_size) {
    const float* x   = (const float*)d_in[0];
    // d_in[1] = x0 (unused: with_linear=False path)
    const float* wts = (const float*)d_in[2];
    const int* ei    = (const int*)d_in[3];   // int32 (JAX x64 disabled)
    const float* Wg  = (const float*)d_in[4];
    const float* bg  = (const float*)d_in[5];
    const float* Wss = (const float*)d_in[6];
    const float* Wsn = (const float*)d_in[7];
    const float* bs  = (const float*)d_in[8];
    const float* Wi  = (const float*)d_in[9];
    const float* bi  = (const float*)d_in[10];
    float* out = (float*)d_out;

    cudaFuncSetAttribute(k_final, cudaFuncAttributeMaxDynamicSharedMemorySize, SMEM_FINAL);

    k_zero<<<(N_NODES * DIM / 4 + 255) / 256, 256>>>();
    k_deg<<<(N_EDGES + 255) / 256, 256>>>(ei);
    k_edge<<<(N_EDGES * 16 + 255) / 256, 256>>>(x, ei);
    k_final<<<(N_NODES + ROWS - 1) / ROWS, 512, SMEM_FINAL>>>(
        x, wts, Wg, bg, Wss, Wsn, bs, Wi, bi, out);
}

// round 5
// speedup vs baseline: 1.1705x; 1.0036x over previous
#include <cuda_runtime.h>
#include <cstdint>

#define N_NODES 100000
#define N_EDGES 1200000
#define DIM 64
#define PAD 66
#define ROWS 128   // nodes per block tile

// Scratch (allocation-free rule: __device__ globals). 16B alignment for
// float4 stores in k_zero and red.global.add.v4.f32 in k_edge.
__device__ __align__(16) float g_A[N_NODES * DIM];  // sum_{e:dst=v} x[src]
__device__ __align__(16) float g_B[N_NODES * DIM];  // sum_{e:dst=v} x[src]*dinv[src]
__device__ float g_sdeg[N_NODES];                   // sum_{e:dst=v} dinv[src]
__device__ int   g_deg[N_NODES];                    // in-degree

typedef unsigned long long ull;

__device__ __forceinline__ ull fma2(ull a, ull b, ull c) {
    ull d;
    asm("fma.rn.f32x2 %0, %1, %2, %3;" : "=l"(d) : "l"(a), "l"(b), "l"(c));
    return d;
}
__device__ __forceinline__ float lo32(ull v) { return __uint_as_float((unsigned)v); }
__device__ __forceinline__ float hi32(ull v) { return __uint_as_float((unsigned)(v >> 32)); }
__device__ __forceinline__ float eluf(float z) { return z > 0.f ? z : expm1f(z); }

__global__ void k_zero() {
    int i = blockIdx.x * blockDim.x + threadIdx.x;
    if (i < N_NODES * DIM / 4) {
        ((float4*)g_A)[i] = make_float4(0.f, 0.f, 0.f, 0.f);
        ((float4*)g_B)[i] = make_float4(0.f, 0.f, 0.f, 0.f);
    }
    if (i < N_NODES) { g_deg[i] = 0; g_sdeg[i] = 0.f; }
}

// edge_index is int32 on device (JAX x64 disabled downgrades jnp.int64).
__global__ void k_deg(const int* __restrict__ ei) {
    int e = blockIdx.x * blockDim.x + threadIdx.x;
    if (e < N_EDGES) atomicAdd(&g_deg[ei[N_EDGES + e]], 1);
}

// Half-warp per edge: 16 lanes x float4 = 64 dims. Vector reds (v4.f32) to L2.
__global__ void k_edge(const float* __restrict__ x, const int* __restrict__ ei) {
    int t = blockIdx.x * blockDim.x + threadIdx.x;
    int e = t >> 4;
    if (e >= N_EDGES) return;
    int lane = t & 15;
    int s = ei[e];
    int d = ei[N_EDGES + e];
    float ds = rsqrtf((float)(g_deg[s] + 1));
    float4 xs = ((const float4*)x)[s * 16 + lane];
    float* pa = g_A + d * DIM + lane * 4;
    float* pb = g_B + d * DIM + lane * 4;
    asm volatile("red.global.add.v4.f32 [%0], {%1,%2,%3,%4};"
                 :: "l"(pa), "f"(xs.x), "f"(xs.y), "f"(xs.z), "f"(xs.w) : "memory");
    asm volatile("red.global.add.v4.f32 [%0], {%1,%2,%3,%4};"
                 :: "l"(pb), "f"(xs.x * ds), "f"(xs.y * ds), "f"(xs.z * ds), "f"(xs.w * ds) : "memory");
    if (lane == 0) atomicAdd(&g_sdeg[d], ds);
}

// Fused epilogue v2: 128-node tiles, 512 threads, 3 sequential matvec passes
// (gcn / sage / gin) so the live register set stays small and ptxas can
// software-pipeline the LDS.64 loads (pragma unroll 4) with 4 warps/SMSP.
//   gcn_pre = p@Wgcn + b_gcn*c1   where p = dinv*(B + dinv*x), c1 = dinv*sdeg + dinv^2
//   sage_pre = x@Wself + m@Wneigh + b_sage   where m = A * (1/max(deg,1))
//   gin_pre  = (x+A)@Wgin + b_gin
//   out = w0*elu(gcn) + w1*elu(sage) + w2*elu(gin)
__global__ void __launch_bounds__(512, 1) k_final(
    const float* __restrict__ x,
    const float* __restrict__ wts,
    const float* __restrict__ Wg,  const float* __restrict__ bg,
    const float* __restrict__ Wss, const float* __restrict__ Wsn, const float* __restrict__ bs,
    const float* __restrict__ Wi,  const float* __restrict__ bi,
    float* __restrict__ out)
{
    extern __shared__ float sh[];
    float* sWg = sh;                  // [64][PAD] transposed: sWg[c*PAD+k] = Wg[k][c]
    float* sWs = sWg + 64 * PAD;
    float* sWn = sWs + 64 * PAD;
    float* sWi = sWn + 64 * PAD;
    float* sP  = sWi + 64 * PAD;      // [ROWS][PAD] node tiles
    float* sX  = sP  + ROWS * PAD;
    float* sM  = sX  + ROWS * PAD;
    float* sG  = sM  + ROWS * PAD;
    float* sBg = sG  + ROWS * PAD;    // [64]
    float* sBs = sBg + 64;
    float* sBi = sBs + 64;
    float* sC1 = sBi + 64;            // [ROWS]
    float* sDi = sC1 + ROWS;
    float* sRd = sDi + ROWS;

    int tid = threadIdx.x;
    int n0 = blockIdx.x * ROWS;

    // Weights transposed into padded shared (coalesced gmem reads)
    for (int idx = tid; idx < 4096; idx += 512) {
        int k = idx >> 6, c = idx & 63;
        int o = c * PAD + k;
        sWg[o] = Wg[idx];
        sWs[o] = Wss[idx];
        sWn[o] = Wsn[idx];
        sWi[o] = Wi[idx];
    }
    if (tid < 64) { sBg[tid] = bg[tid]; sBs[tid] = bs[tid]; sBi[tid] = bi[tid]; }
    if (tid < ROWS) {
        int n = n0 + tid;
        float dg = 0.f, sd = 0.f;
        if (n < N_NODES) { dg = (float)g_deg[n]; sd = g_sdeg[n]; }
        float dinv = rsqrtf(dg + 1.f);
        sC1[tid] = dinv * sd + dinv * dinv;
        sDi[tid] = dinv;
        sRd[tid] = 1.f / fmaxf(dg, 1.f);
    }
    __syncthreads();

    // Fill node tiles p, x, m, x+A
    for (int f = tid; f < ROWS * 16; f += 512) {
        int r = f >> 4, q = f & 15;
        int n = n0 + r;
        float4 x4 = make_float4(0.f, 0.f, 0.f, 0.f), a4 = x4, b4 = x4;
        if (n < N_NODES) {
            x4 = ((const float4*)x)[n * 16 + q];
            a4 = ((const float4*)g_A)[n * 16 + q];
            b4 = ((const float4*)g_B)[n * 16 + q];
        }
        float dinv = sDi[r], rdeg = sRd[r];
        int o = r * PAD + q * 4;
        sP[o + 0] = dinv * (b4.x + dinv * x4.x);
        sP[o + 1] = dinv * (b4.y + dinv * x4.y);
        sP[o + 2] = dinv * (b4.z + dinv * x4.z);
        sP[o + 3] = dinv * (b4.w + dinv * x4.w);
        sX[o + 0] = x4.x; sX[o + 1] = x4.y; sX[o + 2] = x4.z; sX[o + 3] = x4.w;
        sM[o + 0] = a4.x * rdeg; sM[o + 1] = a4.y * rdeg;
        sM[o + 2] = a4.z * rdeg; sM[o + 3] = a4.w * rdeg;
        sG[o + 0] = x4.x + a4.x; sG[o + 1] = x4.y + a4.y;
        sG[o + 2] = x4.z + a4.z; sG[o + 3] = x4.w + a4.w;
    }
    __syncthreads();

    // thread = (tx: cols {tx+16j}, ty: rows {4ty+i}), k packed in f32x2 pairs.
    int tx = tid & 15, ty = tid >> 4;   // ty in 0..31
    int rbase = 4 * ty;

    float rG[4][4], rS[4][4], rI[4][4];

    // ---- pass 1: gcn = P @ Wg ----
    {
        ull acc[4][4];
        #pragma unroll
        for (int i = 0; i < 4; i++)
            #pragma unroll
            for (int j = 0; j < 4; j++) acc[i][j] = 0ull;
        #pragma unroll 4
        for (int kp = 0; kp < 32; kp++) {
            ull nv[4], wv[4];
            #pragma unroll
            for (int i = 0; i < 4; i++) nv[i] = *(const ull*)(sP + (rbase + i) * PAD + 2 * kp);
            #pragma unroll
            for (int j = 0; j < 4; j++) wv[j] = *(const ull*)(sWg + (tx + 16 * j) * PAD + 2 * kp);
            #pragma unroll
            for (int i = 0; i < 4; i++)
                #pragma unroll
                for (int j = 0; j < 4; j++) acc[i][j] = fma2(nv[i], wv[j], acc[i][j]);
        }
        #pragma unroll
        for (int i = 0; i < 4; i++)
            #pragma unroll
            for (int j = 0; j < 4; j++) rG[i][j] = lo32(acc[i][j]) + hi32(acc[i][j]);
    }

    // ---- pass 2: sage = X @ Ws + M @ Wn ----
    {
        ull acc[4][4];
        #pragma unroll
        for (int i = 0; i < 4; i++)
            #pragma unroll
            for (int j = 0; j < 4; j++) acc[i][j] = 0ull;
        #pragma unroll 2
        for (int kp = 0; kp < 32; kp++) {
            ull xv[4], mv[4], ws[4], wn[4];
            #pragma unroll
            for (int i = 0; i < 4; i++) {
                int o = (rbase + i) * PAD + 2 * kp;
                xv[i] = *(const ull*)(sX + o);
                mv[i] = *(const ull*)(sM + o);
            }
            #pragma unroll
            for (int j = 0; j < 4; j++) {
                int o = (tx + 16 * j) * PAD + 2 * kp;
                ws[j] = *(const ull*)(sWs + o);
                wn[j] = *(const ull*)(sWn + o);
            }
            #pragma unroll
            for (int i = 0; i < 4; i++)
                #pragma unroll
                for (int j = 0; j < 4; j++) {
                    acc[i][j] = fma2(xv[i], ws[j], acc[i][j]);
                    acc[i][j] = fma2(mv[i], wn[j], acc[i][j]);
                }
        }
        #pragma unroll
        for (int i = 0; i < 4; i++)
            #pragma unroll
            for (int j = 0; j < 4; j++) rS[i][j] = lo32(acc[i][j]) + hi32(acc[i][j]);
    }

    // ---- pass 3: gin = (X+A) @ Wi ----
    {
        ull acc[4][4];
        #pragma unroll
        for (int i = 0; i < 4; i++)
            #pragma unroll
            for (int j = 0; j < 4; j++) acc[i][j] = 0ull;
        #pragma unroll 4
        for (int kp = 0; kp < 32; kp++) {
            ull nv[4], wv[4];
            #pragma unroll
            for (int i = 0; i < 4; i++) nv[i] = *(const ull*)(sG + (rbase + i) * PAD + 2 * kp);
            #pragma unroll
            for (int j = 0; j < 4; j++) wv[j] = *(const ull*)(sWi + (tx + 16 * j) * PAD + 2 * kp);
            #pragma unroll
            for (int i = 0; i < 4; i++)
                #pragma unroll
                for (int j = 0; j < 4; j++) acc[i][j] = fma2(nv[i], wv[j], acc[i][j]);
        }
        #pragma unroll
        for (int i = 0; i < 4; i++)
            #pragma unroll
            for (int j = 0; j < 4; j++) rI[i][j] = lo32(acc[i][j]) + hi32(acc[i][j]);
    }

    float w0 = wts[0], w1 = wts[1], w2 = wts[2];
    #pragma unroll
    for (int i = 0; i < 4; i++) {
        int r = rbase + i, n = n0 + r;
        if (n >= N_NODES) continue;
        #pragma unroll
        for (int j = 0; j < 4; j++) {
            int c = tx + 16 * j;
            float gcn = rG[i][j] + sBg[c] * sC1[r];
            float sag = rS[i][j] + sBs[c];
            float gin = rI[i][j] + sBi[c];
            out[n * DIM + c] = w0 * eluf(gcn) + w1 * eluf(sag) + w2 * eluf(gin);
        }
    }
}

static const int SMEM_FINAL =
    (4 * 64 * PAD + 4 * ROWS * PAD + 3 * 64 + 3 * ROWS) * (int)sizeof(float);

extern "C" void kernel_launch(void* const* d_in, const int* in_sizes, int n_in,
                              void* d_out, int out_size) {
    const float* x   = (const float*)d_in[0];
    // d_in[1] = x0 (unused: with_linear=False path)
    const float* wts = (const float*)d_in[2];
    const int* ei    = (const int*)d_in[3];   // int32 (JAX x64 disabled)
    const float* Wg  = (const float*)d_in[4];
    const float* bg  = (const float*)d_in[5];
    const float* Wss = (const float*)d_in[6];
    const float* Wsn = (const float*)d_in[7];
    const float* bs  = (const float*)d_in[8];
    const float* Wi  = (const float*)d_in[9];
    const float* bi  = (const float*)d_in[10];
    float* out = (float*)d_out;

    cudaFuncSetAttribute(k_final, cudaFuncAttributeMaxDynamicSharedMemorySize, SMEM_FINAL);

    k_zero<<<(N_NODES * DIM / 4 + 255) / 256, 256>>>();
    k_deg<<<(N_EDGES + 255) / 256, 256>>>(ei);
    k_edge<<<(N_EDGES * 16 + 255) / 256, 256>>>(x, ei);
    k_final<<<(N_NODES + ROWS - 1) / ROWS, 512, SMEM_FINAL>>>(
        x, wts, Wg, bg, Wss, Wsn, bs, Wi, bi, out);
}